// round 17
// baseline (speedup 1.0000x reference)
#include <cuda_runtime.h>

// QAEEncoder R17: R16 with the staging-pad bug fixed (c6p term).
// 2 warps/state (64-thr block), R10 operator pushback, padded staging.
// Amp j[9:0], qubit q <-> bit p=9-q. g(i)=(i^(i>>1))^((i&1)?0x300:0).
// LA: t=j[9:4] (w=j9-bit? no: w=t>>5=j9, lane=j[8:4]), regs m=j[3:0], pack j0.
// LB: w=j0, lane=j[5:1], regs r=j[9:6], pack j6.
// load+norm(LA) -> A q9..q6(reg)+q5,q4(shfl) -> T1 -> A q3..q0(LB reg)
// -> C1 gather+PhA(->LA cplx) -> B q9..q6+q5,q4 -> T2 -> B q3..q0(LB)
// -> measure with (Pi,PhB)-conjugated ops (warp-local); stage-C folded.
// Pads: floats a32(i)=i+2*(i>>5)  [for i=64r+c6: 68r + c6 + 2*(c6>>5)];
//       u64    a16(i)=i+(i>>4)    [for i=64r+c6: 68r + c6 + (c6>>4)].

constexpr int NT = 64;
using u64 = unsigned long long;

__device__ float2 d_phA[1024];   // [(j&15)*64 + (j>>4)]
__device__ float2 d_g[33];       // [0,20)=gAB, [20,26)=gC, [26,33)=exp(i w[40+m])

__device__ __forceinline__ u64 pk2(float a, float b) {
    u64 r; asm("mov.b64 %0,{%1,%2};" : "=l"(r) : "f"(a), "f"(b)); return r;
}
__device__ __forceinline__ void upk2(u64 v, float& a, float& b) {
    asm("mov.b64 {%0,%1},%2;" : "=f"(a), "=f"(b) : "l"(v));
}
__device__ __forceinline__ u64 mul2(u64 a, u64 b) {
    u64 d; asm("mul.rn.f32x2 %0,%1,%2;" : "=l"(d) : "l"(a), "l"(b)); return d;
}
__device__ __forceinline__ u64 fma2(u64 a, u64 b, u64 c) {
    u64 d; asm("fma.rn.f32x2 %0,%1,%2,%3;" : "=l"(d) : "l"(a), "l"(b), "l"(c)); return d;
}
__device__ __forceinline__ u64 add2(u64 a, u64 b) {
    u64 d; asm("add.rn.f32x2 %0,%1,%2;" : "=l"(d) : "l"(a), "l"(b)); return d;
}
__device__ __forceinline__ u64 swp(u64 v) {
    float a, b; upk2(v, a, b); return pk2(b, a);
}
__device__ __forceinline__ float wsum(float v) {
#pragma unroll
    for (int o = 16; o; o >>= 1) v += __shfl_xor_sync(0xffffffffu, v, o);
    return v;
}
__device__ __forceinline__ u64 wsum2(u64 v) {
#pragma unroll
    for (int o = 16; o; o >>= 1) v = add2(v, __shfl_xor_sync(0xffffffffu, v, o));
    return v;
}

__global__ void qae_setup(const float* __restrict__ w)
{
    int t = threadIdx.x;   // 1024
    {
        int gi = (t ^ (t >> 1)) ^ ((t & 1) ? 0x300 : 0);
        float phA = 0.0f;
#pragma unroll
        for (int p = 0; p < 10; p++)
            phA += w[10 + 9 - p] * (((gi >> p) & 1) ? 0.5f : -0.5f);
        float c, s; sincosf(phA, &s, &c);
        d_phA[(t & 15) * 64 + (t >> 4)] = make_float2(c, s);
    }
    if (t < 20) {
        int st = t / 10, q = t % 10;
        float th = st ? (w[20 + q] + w[30 + q]) : w[q];
        float c, s; sincosf(0.5f * th, &s, &c);
        d_g[t] = make_float2(c, s);
    } else if (t < 26) {
        float c, s; sincosf(w[50 + (t - 20)], &s, &c);
        d_g[t] = make_float2(c, s);
    } else if (t < 33) {
        float c, s; sincosf(w[40 + (t - 26)], &s, &c);
        d_g[t] = make_float2(c, s);
    }
}

__global__ void __launch_bounds__(NT, 16)
qae17_kernel(const float* __restrict__ x,
             float* __restrict__ out,
             int B, int D)
{
    __shared__ u64    sbuf[1088];
    __shared__ float2 sg[33];
    __shared__ float  sred[2];
    __shared__ float  sacc[36];

    const int t    = threadIdx.x;
    const int w    = t >> 5;
    const int lane = t & 31;
    const int b    = blockIdx.x;

    if (t < 33) sg[t] = d_g[t];

    float* bufr = (float*)sbuf;
    u64*   bufu = sbuf;

    // ---- load LA (16 contiguous amps/thread) + block norm ------------------
    u64 PA[8];
    float ss = 0.0f;
    const int idx0 = t * 16;
    const float* xrow = x + (size_t)b * D + idx0;
    if (idx0 + 16 <= D) {
#pragma unroll
        for (int k = 0; k < 4; k++) {
            float4 v = ((const float4*)xrow)[k];
            PA[2 * k]     = pk2(v.x, v.y);
            PA[2 * k + 1] = pk2(v.z, v.w);
            ss += v.x * v.x + v.y * v.y + v.z * v.z + v.w * v.w;
        }
    } else if (idx0 < D) {
#pragma unroll
        for (int k = 0; k < 8; k++) {
            int i0 = idx0 + 2 * k;
            float lo = (i0     < D) ? xrow[2 * k]     : 0.0f;
            float hi = (i0 + 1 < D) ? xrow[2 * k + 1] : 0.0f;
            PA[k] = pk2(lo, hi);
            ss += lo * lo + hi * hi;
        }
    } else {
#pragma unroll
        for (int k = 0; k < 8; k++) PA[k] = 0ull;
    }
    ss = wsum(ss);
    if (lane == 0) sred[w] = ss;
    __syncthreads();
    float inv = 1.0f / fmaxf(sqrtf(sred[0] + sred[1]), 1e-8f);

    // ---- stage A LA: q9 in-pack (norm folded), q8..q6 reg, q5,q4 shfl ------
    {
        float2 g = sg[9];
        float ci = g.x * inv, si = g.y * inv;
        u64 cc = pk2(ci, ci), ns = pk2(-si, si);
#pragma unroll
        for (int k = 0; k < 8; k++) PA[k] = fma2(swp(PA[k]), ns, mul2(PA[k], cc));
    }
#pragma unroll
    for (int p = 1; p < 4; p++) {
        float2 g = sg[9 - p];
        u64 cc = pk2(g.x, g.x), sp = pk2(g.y, g.y), sn = pk2(-g.y, -g.y);
        int m = 1 << (p - 1);
#pragma unroll
        for (int k = 0; k < 8; k++) if (!(k & m)) {
            u64 a = PA[k], bb = PA[k | m];
            PA[k]     = fma2(bb, sn, mul2(a, cc));
            PA[k | m] = fma2(a, sp, mul2(bb, cc));
        }
    }
#pragma unroll
    for (int d = 0; d < 2; d++) {
        float2 g = sg[5 - d];
        int msk = 1 << d;
        float sgn = (lane & msk) ? g.y : -g.y;
        u64 cc = pk2(g.x, g.x), sv = pk2(sgn, sgn);
#pragma unroll
        for (int k = 0; k < 8; k++)
            PA[k] = fma2(__shfl_xor_sync(0xffffffffu, PA[k], msk), sv, mul2(PA[k], cc));
    }

    // ---- T1: LA -> LB (real, a32) ------------------------------------------
    {
        int u0 = 8 * t + (t >> 1);      // u64 index of floats a32(16t+2k),+1
#pragma unroll
        for (int k = 0; k < 8; k++) bufu[u0 + k] = PA[k];
    }
    __syncthreads();
    const int c6  = lane * 2 + w;               // j[5:0]
    const int c6p = c6 + 2 * (c6 >> 5);         // pad term for a32 reads/stores
    u64 PB[8];
    {
        float v[16];
#pragma unroll
        for (int r = 0; r < 16; r++) v[r] = bufr[68 * r + c6p];
#pragma unroll
        for (int k = 0; k < 8; k++) PB[k] = pk2(v[2 * k], v[2 * k + 1]);
    }
    __syncthreads();

    // ---- stage A LB: q3 in-pack, q2..q0 reg --------------------------------
    {
        float2 g = sg[3];
        u64 cc = pk2(g.x, g.x), ns = pk2(-g.y, g.y);
#pragma unroll
        for (int k = 0; k < 8; k++) PB[k] = fma2(swp(PB[k]), ns, mul2(PB[k], cc));
    }
#pragma unroll
    for (int p = 0; p < 3; p++) {
        float2 g = sg[2 - p];
        u64 cc = pk2(g.x, g.x), sp = pk2(g.y, g.y), sn = pk2(-g.y, -g.y);
        int m = 1 << p;
#pragma unroll
        for (int k = 0; k < 8; k++) if (!(k & m)) {
            u64 a = PB[k], bb = PB[k | m];
            PB[k]     = fma2(bb, sn, mul2(a, cc));
            PB[k | m] = fma2(a, sp, mul2(bb, cc));
        }
    }

    // ---- C1: store LB (a32), gather g + PhA -> LA complex ------------------
#pragma unroll
    for (int k = 0; k < 8; k++) {
        float lo, hi; upk2(PB[k], lo, hi);
        bufr[68 * (2 * k) + c6p]     = lo;
        bufr[68 * (2 * k + 1) + c6p] = hi;
    }
    __syncthreads();
    u64 P[16];
    {
        const u64* phA = (const u64*)d_phA;
#pragma unroll
        for (int m = 0; m < 16; m++) {
            int j  = t * 16 + m;
            int gj = (j ^ (j >> 1)) ^ ((j & 1) ? 0x300 : 0);
            float rv = bufr[gj + 2 * (gj >> 5)];
            P[m] = mul2(pk2(rv, rv), __ldg(&phA[m * 64 + t]));
        }
    }
    __syncthreads();

    // ---- stage B LA: q9..q6 reg, q5,q4 shfl (complex) ----------------------
#pragma unroll
    for (int p = 0; p < 4; p++) {
        float2 g = sg[19 - p];
        u64 cc = pk2(g.x, g.x), sp = pk2(g.y, g.y), sn = pk2(-g.y, -g.y);
        int m = 1 << p;
#pragma unroll
        for (int r = 0; r < 16; r++) if (!(r & m)) {
            u64 a = P[r], bb = P[r | m];
            P[r]     = fma2(bb, sn, mul2(a, cc));
            P[r | m] = fma2(a, sp, mul2(bb, cc));
        }
    }
#pragma unroll
    for (int d = 0; d < 2; d++) {
        float2 g = sg[15 - d];
        int msk = 1 << d;
        float sgn = (lane & msk) ? g.y : -g.y;
        u64 cc = pk2(g.x, g.x), sv = pk2(sgn, sgn);
#pragma unroll
        for (int r = 0; r < 16; r++)
            P[r] = fma2(__shfl_xor_sync(0xffffffffu, P[r], msk), sv, mul2(P[r], cc));
    }

    // ---- T2: LA -> LB (u64, a16) -------------------------------------------
#pragma unroll
    for (int m = 0; m < 16; m++) bufu[17 * t + m] = P[m];
    __syncthreads();
    {
        int c16 = c6 + (c6 >> 4);
#pragma unroll
        for (int r = 0; r < 16; r++) P[r] = bufu[68 * r + c16];
    }

    // ---- stage B LB: q3..q0 reg --------------------------------------------
#pragma unroll
    for (int p = 0; p < 4; p++) {
        float2 g = sg[13 - p];
        u64 cc = pk2(g.x, g.x), sp = pk2(g.y, g.y), sn = pk2(-g.y, -g.y);
        int m = 1 << p;
#pragma unroll
        for (int r = 0; r < 16; r++) if (!(r & m)) {
            u64 a = P[r], bb = P[r | m];
            P[r]     = fma2(bb, sn, mul2(a, cc));
            P[r | m] = fma2(a, sp, mul2(bb, cc));
        }
    }

    // ======= measurement (LB), operators conjugated by (Pi, PhB) ============
    const int lanepar = __popc(lane) & 1;
    const int lane2b  = (lane >> 2) & 1;
    const int lane3b  = (lane >> 3) & 1;
    const int lane4b  = (lane >> 4) & 1;

    float zq[6];
    {
        float A0 = 0, A1 = 0, A2 = 0, A3 = 0;
#pragma unroll
        for (int r = 0; r < 16; r++) {
            float lo, hi; upk2(mul2(P[r], P[r]), lo, hi);
            float nv = lo + hi;
            A0 = (__popc(r & 0x7) & 1) ? A0 - nv : A0 + nv;
            A1 = (__popc(r & 0xC) & 1) ? A1 - nv : A1 + nv;
            A2 = (__popc(r & 0xE) & 1) ? A2 - nv : A2 + nv;
            A3 = (__popc(r & 0xF) & 1) ? A3 - nv : A3 + nv;
        }
        zq[0] = (lanepar ^ w) ? -A0 : A0;
        zq[1] = A1; zq[2] = A2; zq[3] = A3;
        zq[4] = lane4b ? -A3 : A3;
        zq[5] = (lane4b ^ lane3b) ? -A3 : A3;
    }

    float ReS[6], ImS[6];
    // ---- q0..q2: reg pairs, 4 phase buckets (Ea=sg[27+q], Eb=sg[26+q]) -----
    {
        const int DR[3] = {0xC, 0x6, 0x3};
        const int LO[3] = {0x4, 0x2, 0x1};
        const int KM[3] = {0x7, 0xC, 0xE};
        const int BA[3] = {2, 1, 0};
#pragma unroll
        for (int q = 0; q < 3; q++) {
            const int dr = DR[q];
            u64 d0=0ull,d1=0ull,d2=0ull,d3=0ull, c0=0ull,c1=0ull,c2=0ull,c3=0ull;
#pragma unroll
            for (int r = 0; r < 16; r++) if (!(r & LO[q])) {
                int k  = __popc(r & KM[q]) & 1;
                int ra = k ? (r ^ dr) : r;
                u64 a = P[ra], bb = P[ra ^ dr], bs = swp(bb);
                int bkt = ((ra >> BA[q]) & 1) | (((ra >> (BA[q] + 1)) & 1) << 1);
                if      (bkt == 0) { d0 = fma2(a, bb, d0); c0 = fma2(a, bs, c0); }
                else if (bkt == 1) { d1 = fma2(a, bb, d1); c1 = fma2(a, bs, c1); }
                else if (bkt == 2) { d2 = fma2(a, bb, d2); c2 = fma2(a, bs, c2); }
                else               { d3 = fma2(a, bb, d3); c3 = fma2(a, bs, c3); }
            }
            float2 Ea = sg[27 + q], Eb = sg[26 + q];
            float Re = 0.0f, Im = 0.0f;
            u64 AD[4] = {d0, d1, d2, d3}, AC[4] = {c0, c1, c2, c3};
#pragma unroll
            for (int tt = 0; tt < 4; tt++) {
                int ja = tt & 1, jb = (tt >> 1) & 1;
                float sa = ja ? -Ea.y : Ea.y;
                float sb = jb ? -Eb.y : Eb.y;
                float cosd = Ea.x * Eb.x - sa * sb;
                float sind = sa * Eb.x + sb * Ea.x;
                float dl, dh, cl, ch; upk2(AD[tt], dl, dh); upk2(AC[tt], cl, ch);
                float Rb = dl + dh, Ib = cl - ch;
                Re += Rb * cosd - Ib * sind;
                Im += Rb * sind + Ib * cosd;
            }
            ReS[q] = Re;
            ImS[q] = (q == 0 && (lanepar ^ w)) ? -Im : Im;
        }
    }
    // ---- q3: mixed pair (r^1, lane^16); canonical par(r&0xF)==0 ------------
    {
        u64 d0=0ull, c0=0ull, d1=0ull, c1=0ull;
#pragma unroll
        for (int r = 0; r < 16; r++) if (!(__popc(r & 0xF) & 1)) {
            u64 bb = __shfl_xor_sync(0xffffffffu, P[r ^ 1], 16), bs = swp(bb);
            if (r & 1) { d1 = fma2(P[r], bb, d1); c1 = fma2(P[r], bs, c1); }
            else       { d0 = fma2(P[r], bb, d0); c0 = fma2(P[r], bs, c0); }
        }
        float2 E6 = sg[29], E5 = sg[30];
        float dl, dh, cl, ch;
        upk2(d0, dl, dh); upk2(c0, cl, ch);
        float R0 = dl + dh, I0 = cl - ch;
        upk2(d1, dl, dh); upk2(c1, cl, ch);
        float R1 = dl + dh, I1 = cl - ch;
        float ReA = (R0 * E6.x - I0 * E6.y) + (R1 * E6.x + I1 * E6.y);
        float ImA = (R0 * E6.y + I0 * E6.x) + (I1 * E6.x - R1 * E6.y);
        float s5 = lane4b ? -E5.y : E5.y;
        ReS[3] = ReA * E5.x - ImA * s5;
        ImS[3] = ReA * s5 + ImA * E5.x;
    }
    // ---- q4: lane pair xor 24; canonical: par(r&0xF) == lane4b -------------
    {
        u64 dE=0ull, cE=0ull, dO=0ull, cO=0ull;
#pragma unroll
        for (int r = 0; r < 16; r++) {
            u64 bb = __shfl_xor_sync(0xffffffffu, P[r], 24), bs = swp(bb);
            if (__popc(r & 0xF) & 1) { dO = fma2(P[r], bb, dO); cO = fma2(P[r], bs, cO); }
            else                     { dE = fma2(P[r], bb, dE); cE = fma2(P[r], bs, cE); }
        }
        u64 ad = lane4b ? dO : dE, ac = lane4b ? cO : cE;
        float dl, dh, cl, ch; upk2(ad, dl, dh); upk2(ac, cl, ch);
        float Re = dl + dh, Im = cl - ch;
        float2 E4 = sg[31], E5 = sg[30];
        float s4 = lane3b ? -E4.y : E4.y;
        float s5 = lane4b ? -E5.y : E5.y;
        float cosd = E4.x * E5.x - s4 * s5;
        float sind = s4 * E5.x + s5 * E4.x;
        ReS[4] = Re * cosd - Im * sind;
        ImS[4] = Re * sind + Im * cosd;
    }
    // ---- q5: lane pair xor 12; canonical: par(r&0xF) == lane3b^lane4b ------
    {
        u64 dE=0ull, cE=0ull, dO=0ull, cO=0ull;
#pragma unroll
        for (int r = 0; r < 16; r++) {
            u64 bb = __shfl_xor_sync(0xffffffffu, P[r], 12), bs = swp(bb);
            if (__popc(r & 0xF) & 1) { dO = fma2(P[r], bb, dO); cO = fma2(P[r], bs, cO); }
            else                     { dE = fma2(P[r], bb, dE); cE = fma2(P[r], bs, cE); }
        }
        int sel = lane3b ^ lane4b;
        u64 ad = sel ? dO : dE, ac = sel ? cO : cE;
        float dl, dh, cl, ch; upk2(ad, dl, dh); upk2(ac, cl, ch);
        float Re = dl + dh, Im = cl - ch;
        float2 E3 = sg[32], E4 = sg[31];
        float s3 = lane2b ? -E3.y : E3.y;
        float s4 = lane3b ? -E4.y : E4.y;
        float cosd = E3.x * E4.x - s3 * s4;
        float sind = s3 * E4.x + s4 * E3.x;
        ReS[5] = Re * cosd - Im * sind;
        ImS[5] = Re * sind + Im * cosd;
    }

    // ---- reductions: warp wsum2, then 2-warp combine via shared ------------
#pragma unroll
    for (int q = 0; q < 6; q++) {
        u64 ri = wsum2(pk2(ReS[q], ImS[q]));
        float zr = wsum(zq[q]);
        if (lane == 0) {
            float re, im; upk2(ri, re, im);
            sacc[w * 18 + q]      = re;
            sacc[w * 18 + 6 + q]  = im;
            sacc[w * 18 + 12 + q] = zr;
        }
    }
    __syncthreads();
    if (t < 6) {
        int q = t;
        float Re = sacc[q]      + sacc[18 + q];
        float Im = sacc[6 + q]  + sacc[24 + q];
        float Z  = sacc[12 + q] + sacc[30 + q];
        float X = 2.0f * Re, Y = 2.0f * Im;
        float2 gc = sg[20 + q];
        float* o = out + (size_t)b * 18;
        o[q]      = gc.x * X + gc.y * Z;
        o[6 + q]  = Y;
        o[12 + q] = gc.x * Z - gc.y * X;
    }
}

extern "C" void kernel_launch(void* const* d_in, const int* in_sizes, int n_in,
                              void* d_out, int out_size)
{
    int ix = 0, iw = 1;
    if (n_in >= 2 && in_sizes[0] < in_sizes[1]) { ix = 1; iw = 0; }
    const float* x = (const float*)d_in[ix];
    const float* w = (const float*)d_in[iw];
    float* out = (float*)d_out;

    int B = out_size / 18;
    int D = (B > 0) ? (in_sizes[ix] / B) : 0;

    qae_setup<<<1, 1024>>>(w);
    qae17_kernel<<<B, NT>>>(x, out, B, D);
}